// round 1
// baseline (speedup 1.0000x reference)
#include <cuda_runtime.h>

// out = noised + (2*0.05) * noise, elementwise over 50,331,648 fp32.
// HBM-bound streaming kernel: float4 vectorized, one vec4 per thread.

__global__ void __launch_bounds__(256) gnoise_kernel(
    const float4* __restrict__ noised,
    const float4* __restrict__ noise,
    float4* __restrict__ out,
    int n4)
{
    int i = blockIdx.x * blockDim.x + threadIdx.x;
    if (i < n4) {
        float4 a = noised[i];
        float4 b = noise[i];
        const float s = 0.1f;
        float4 r;
        r.x = fmaf(s, b.x, a.x);
        r.y = fmaf(s, b.y, a.y);
        r.z = fmaf(s, b.z, a.z);
        r.w = fmaf(s, b.w, a.w);
        out[i] = r;
    }
}

// Tail handler in case n is not divisible by 4 (it is here, but be safe).
__global__ void gnoise_tail(
    const float* __restrict__ noised,
    const float* __restrict__ noise,
    float* __restrict__ out,
    int start, int n)
{
    int i = start + blockIdx.x * blockDim.x + threadIdx.x;
    if (i < n) {
        out[i] = fmaf(0.1f, noise[i], noised[i]);
    }
}

extern "C" void kernel_launch(void* const* d_in, const int* in_sizes, int n_in,
                              void* d_out, int out_size)
{
    const float* noised = (const float*)d_in[0];
    const float* noise  = (const float*)d_in[1];
    float* out = (float*)d_out;
    int n = in_sizes[0];

    int n4 = n / 4;
    if (n4 > 0) {
        int threads = 256;
        int blocks = (n4 + threads - 1) / threads;
        gnoise_kernel<<<blocks, threads>>>(
            (const float4*)noised, (const float4*)noise, (float4*)out, n4);
    }
    int rem = n - n4 * 4;
    if (rem > 0) {
        gnoise_tail<<<1, 32>>>(noised, noise, out, n4 * 4, n);
    }
}